// round 5
// baseline (speedup 1.0000x reference)
#include <cuda_runtime.h>
#include <cuda_fp16.h>
#include <cstdint>

constexpr int N_NODES = 100000;
constexpr int N_EDGES = 3200000;
constexpr int IN_CH   = 128;
constexpr int HID     = 16;
constexpr int OUT_CH  = 64;
constexpr int SCAN_BLK = 256;
constexpr int N_BLK1   = (N_NODES + SCAN_BLK - 1) / SCAN_BLK;   // 391

// ---------------- scratch (device globals; allocation-free) ----------------
__device__ __align__(16) int    g_deg   [N_NODES];
__device__ __align__(16) float  g_dinv  [N_NODES];
__device__ __align__(16) int    g_off   [N_NODES + 1];
__device__ __align__(16) int    g_cursor[N_NODES];
__device__ __align__(16) int    g_bsum  [N_BLK1];
__device__ __align__(16) int    g_csr   [N_EDGES];              // src per in-edge, grouped by dst
__device__ __align__(16) __half g_h1h   [N_NODES * HID];        // (x@W1) * dinv[row], fp16
__device__ __align__(16) __half g_gsh   [N_NODES * HID];        // relu(...) * dinv[row], fp16
__device__ int g_is32;

// ---------------- prep ----------------

// zero degrees + detect edge-index dtype (JAX without x64 silently yields
// int32 despite the int64 annotation). Single deterministic writer for flag.
__global__ void k_init_detect(const long long* __restrict__ ei) {
    int i = blockIdx.x * blockDim.x + threadIdx.x;
    if (i < N_NODES) g_deg[i] = 0;
    if (blockIdx.x == 0 && threadIdx.x < 32) {
        bool bad = false;
        for (int t = threadIdx.x; t < 256; t += 32) {
            long long v = ei[t];
            bad |= (v < 0 || v >= (long long)N_NODES);
        }
        unsigned m = __ballot_sync(0xffffffffu, bad);
        if (threadIdx.x == 0) g_is32 = (m != 0u) ? 1 : 0;
    }
}

__global__ void k_count(const void* __restrict__ eiv) {
    int e = blockIdx.x * blockDim.x + threadIdx.x;
    if (e >= N_EDGES) return;
    int d;
    if (g_is32) d = ((const int*)eiv)[N_EDGES + e];
    else        d = (int)((const long long*)eiv)[N_EDGES + e];
    d = min(max(d, 0), N_NODES - 1);
    atomicAdd(&g_deg[d], 1);
}

// exclusive scan of g_deg -> g_off, plus dinv (deg incl. self-loop)
__global__ void k_scan1_dinv() {
    __shared__ int s[SCAN_BLK];
    int i = blockIdx.x * SCAN_BLK + threadIdx.x;
    int v = (i < N_NODES) ? g_deg[i] : 0;
    if (i < N_NODES) g_dinv[i] = rsqrtf((float)(v + 1));
    s[threadIdx.x] = v;
    __syncthreads();
    for (int o = 1; o < SCAN_BLK; o <<= 1) {
        int t = (threadIdx.x >= o) ? s[threadIdx.x - o] : 0;
        __syncthreads();
        s[threadIdx.x] += t;
        __syncthreads();
    }
    if (i < N_NODES) g_off[i] = s[threadIdx.x] - v;               // exclusive
    if (threadIdx.x == SCAN_BLK - 1) g_bsum[blockIdx.x] = s[threadIdx.x];
}

__global__ void k_scan2() {     // 1 block, 512 threads; scan 391 block sums
    __shared__ int s[512];
    int v = (threadIdx.x < N_BLK1) ? g_bsum[threadIdx.x] : 0;
    s[threadIdx.x] = v;
    __syncthreads();
    for (int o = 1; o < 512; o <<= 1) {
        int t = (threadIdx.x >= o) ? s[threadIdx.x - o] : 0;
        __syncthreads();
        s[threadIdx.x] += t;
        __syncthreads();
    }
    if (threadIdx.x < N_BLK1) g_bsum[threadIdx.x] = s[threadIdx.x] - v;  // exclusive
}

__global__ void k_scan3() {
    int i = blockIdx.x * blockDim.x + threadIdx.x;
    if (i < N_NODES) {
        int o = g_off[i] + g_bsum[i / SCAN_BLK];
        g_off[i] = o;
        g_cursor[i] = o;
    }
    if (i == 0) g_off[N_NODES] = N_EDGES;
}

__global__ void k_fill(const void* __restrict__ eiv) {
    int e = blockIdx.x * blockDim.x + threadIdx.x;
    if (e >= N_EDGES) return;
    int s, d;
    if (g_is32) {
        const int* p = (const int*)eiv;
        s = p[e]; d = p[N_EDGES + e];
    } else {
        const long long* p = (const long long*)eiv;
        s = (int)p[e]; d = (int)p[N_EDGES + e];
    }
    s = min(max(s, 0), N_NODES - 1);
    d = min(max(d, 0), N_NODES - 1);
    int pos = atomicAdd(&g_cursor[d], 1);
    g_csr[pos] = s;
}

// ---------------- layer 1 GEMM: h1h = fp16( (x @ W1) * dinv[row] ) --------
__global__ void k_gemm1(const float* __restrict__ x, const float* __restrict__ W1) {
    __shared__ float sW[IN_CH * HID];   // 8 KB
    for (int t = threadIdx.x; t < IN_CH * HID; t += blockDim.x) sW[t] = W1[t];
    __syncthreads();

    int row = blockIdx.x * blockDim.x + threadIdx.x;
    if (row >= N_NODES) return;

    float acc[HID];
#pragma unroll
    for (int j = 0; j < HID; j++) acc[j] = 0.f;

    const float4* xr = reinterpret_cast<const float4*>(x + (size_t)row * IN_CH);
#pragma unroll 4
    for (int k4 = 0; k4 < IN_CH / 4; k4++) {
        float4 v = xr[k4];
        const float* w = &sW[k4 * 4 * HID];
#pragma unroll
        for (int j = 0; j < HID; j++)
            acc[j] += v.x * w[j] + v.y * w[HID + j] + v.z * w[2 * HID + j] + v.w * w[3 * HID + j];
    }

    float dv = g_dinv[row];
    __half2 hh[8];
#pragma unroll
    for (int j = 0; j < 8; j++)
        hh[j] = __floats2half2_rn(acc[2 * j] * dv, acc[2 * j + 1] * dv);
    uint4* H = reinterpret_cast<uint4*>(g_h1h);
    H[row * 2 + 0] = *reinterpret_cast<uint4*>(&hh[0]);
    H[row * 2 + 1] = *reinterpret_cast<uint4*>(&hh[4]);
}

// ---------------- gather helpers ----------------
__device__ __forceinline__ void acc_add_u4(float* acc, uint4 u) {
    float2 f;
    f = __half22float2(*reinterpret_cast<__half2*>(&u.x)); acc[0] += f.x; acc[1] += f.y;
    f = __half22float2(*reinterpret_cast<__half2*>(&u.y)); acc[2] += f.x; acc[3] += f.y;
    f = __half22float2(*reinterpret_cast<__half2*>(&u.z)); acc[4] += f.x; acc[5] += f.y;
    f = __half22float2(*reinterpret_cast<__half2*>(&u.w)); acc[6] += f.x; acc[7] += f.y;
}

// warp per node; 16 groups of 2 lanes; lane q in {0,1} owns channels q*8..q*8+7
// grid = N_NODES/8 blocks of 256 (exact: 100000 = 12500*8)

// ---------------- gather layer 1 (fused bias+relu+rescale) ----------------
__global__ void k_gather1(const float* __restrict__ b1) {
    int nid = (blockIdx.x * blockDim.x + threadIdx.x) >> 5;
    int lane = threadIdx.x & 31;
    int grp = lane >> 1, q = lane & 1;

    int beg = g_off[nid], end = g_off[nid + 1];
    const uint4* H = reinterpret_cast<const uint4*>(g_h1h);

    float acc[8];
#pragma unroll
    for (int j = 0; j < 8; j++) acc[j] = 0.f;
    if (grp == 0) acc_add_u4(acc, H[nid * 2 + q]);      // self-loop

    for (int i = beg + grp; i < end; i += 16) {
        int s = g_csr[i];
        acc_add_u4(acc, H[s * 2 + q]);
    }
#pragma unroll
    for (int m = 16; m >= 2; m >>= 1)
#pragma unroll
        for (int j = 0; j < 8; j++)
            acc[j] += __shfl_xor_sync(0xffffffffu, acc[j], m);

    if (lane < 2) {
        float dv = g_dinv[nid];
        const float* bp = b1 + q * 8;
        __half2 hh[4];
#pragma unroll
        for (int j = 0; j < 4; j++) {
            float r0 = fmaxf(acc[2 * j]     * dv + bp[2 * j],     0.f) * dv;
            float r1 = fmaxf(acc[2 * j + 1] * dv + bp[2 * j + 1], 0.f) * dv;
            hh[j] = __floats2half2_rn(r0, r1);
        }
        reinterpret_cast<uint4*>(g_gsh)[nid * 2 + q] = *reinterpret_cast<uint4*>(&hh[0]);
    }
}

// ---------------- gather layer 2 fused with GEMM2 (+b2) ----------------
__global__ void k_gather2_gemm2(const float* __restrict__ W2,
                                const float* __restrict__ b2,
                                float* __restrict__ out) {
    __shared__ float sW[HID * OUT_CH];                 // 4 KB
    __shared__ float s_a[8][HID];
    for (int t = threadIdx.x; t < HID * OUT_CH; t += blockDim.x) sW[t] = W2[t];
    __syncthreads();

    int w = threadIdx.x >> 5;
    int nid = blockIdx.x * 8 + w;                      // grid exact, no tail
    int lane = threadIdx.x & 31;
    int grp = lane >> 1, q = lane & 1;

    int beg = g_off[nid], end = g_off[nid + 1];
    const uint4* G = reinterpret_cast<const uint4*>(g_gsh);

    float acc[8];
#pragma unroll
    for (int j = 0; j < 8; j++) acc[j] = 0.f;
    if (grp == 0) acc_add_u4(acc, G[nid * 2 + q]);      // self-loop

    for (int i = beg + grp; i < end; i += 16) {
        int s = g_csr[i];
        acc_add_u4(acc, G[s * 2 + q]);
    }
#pragma unroll
    for (int m = 16; m >= 2; m >>= 1)
#pragma unroll
        for (int j = 0; j < 8; j++)
            acc[j] += __shfl_xor_sync(0xffffffffu, acc[j], m);

    if (lane < 2) {
        float dv = g_dinv[nid];
#pragma unroll
        for (int j = 0; j < 8; j++) s_a[w][q * 8 + j] = acc[j] * dv;
    }
    __syncwarp();

    // each lane computes cols {lane, lane+32}
    float a0 = b2[lane], a1 = b2[lane + 32];
#pragma unroll
    for (int k = 0; k < HID; k++) {
        float av = s_a[w][k];
        a0 += av * sW[k * OUT_CH + lane];
        a1 += av * sW[k * OUT_CH + lane + 32];
    }
    out[(size_t)nid * OUT_CH + lane]      = a0;
    out[(size_t)nid * OUT_CH + lane + 32] = a1;
}

// ---------------- launch ----------------
extern "C" void kernel_launch(void* const* d_in, const int* in_sizes, int n_in,
                              void* d_out, int out_size) {
    const float* x  = (const float*)d_in[0];
    const void*  ei = (const void*)d_in[1];
    const float* W1 = (const float*)d_in[2];
    const float* b1 = (const float*)d_in[3];
    const float* W2 = (const float*)d_in[4];
    const float* b2 = (const float*)d_in[5];
    float*       out = (float*)d_out;

    const int TB = 256;
    k_init_detect<<<(N_NODES + TB - 1) / TB, TB>>>((const long long*)ei);
    k_count<<<(N_EDGES + TB - 1) / TB, TB>>>(ei);
    k_scan1_dinv<<<N_BLK1, SCAN_BLK>>>();
    k_scan2<<<1, 512>>>();
    k_scan3<<<(N_NODES + TB - 1) / TB, TB>>>();
    k_fill<<<(N_EDGES + TB - 1) / TB, TB>>>(ei);

    k_gemm1<<<(N_NODES + 127) / 128, 128>>>(x, W1);
    k_gather1<<<N_NODES / 8, TB>>>(b1);                 // 100000 = 12500*8 exact
    k_gather2_gemm2<<<N_NODES / 8, TB>>>(W2, b2, out);
}

// round 6
// speedup vs baseline: 1.0807x; 1.0807x over previous
#include <cuda_runtime.h>
#include <cstdint>

constexpr int N_NODES = 100000;
constexpr int N_EDGES = 3200000;
constexpr int IN_CH   = 128;
constexpr int HID     = 16;
constexpr int OUT_CH  = 64;
constexpr int SCAN_BLK = 256;
constexpr int N_BLK1   = (N_NODES + SCAN_BLK - 1) / SCAN_BLK;   // 391

// ---------------- scratch (device globals; allocation-free) ----------------
__device__ __align__(16) int   g_deg   [N_NODES];
__device__ __align__(16) float g_dinv  [N_NODES];
__device__ __align__(16) int   g_off   [N_NODES + 1];
__device__ __align__(16) int   g_cursor[N_NODES];
__device__ __align__(16) int   g_bsum  [N_BLK1];
__device__ __align__(16) int   g_csr   [N_EDGES];               // src per in-edge, grouped by dst
__device__ __align__(16) float g_h1s   [N_NODES * HID];         // (x@W1) * dinv[row]
__device__ __align__(16) float g_gs    [N_NODES * HID];         // relu(...) * dinv[row]
__device__ int g_is32;

// ---------------- prep ----------------

// zero degrees + detect edge-index dtype (JAX without x64 silently yields
// int32 despite the int64 annotation). Single deterministic writer.
__global__ void k_init_detect(const long long* __restrict__ ei) {
    int i = blockIdx.x * blockDim.x + threadIdx.x;
    if (i < N_NODES) g_deg[i] = 0;
    if (blockIdx.x == 0 && threadIdx.x < 32) {
        bool bad = false;
        for (int t = threadIdx.x; t < 256; t += 32) {
            long long v = ei[t];
            bad |= (v < 0 || v >= (long long)N_NODES);
        }
        unsigned m = __ballot_sync(0xffffffffu, bad);
        if (threadIdx.x == 0) g_is32 = (m != 0u) ? 1 : 0;
    }
}

__global__ void k_count(const void* __restrict__ eiv) {
    int e = blockIdx.x * blockDim.x + threadIdx.x;
    if (e >= N_EDGES) return;
    int d;
    if (g_is32) d = ((const int*)eiv)[N_EDGES + e];
    else        d = (int)((const long long*)eiv)[N_EDGES + e];
    d = min(max(d, 0), N_NODES - 1);
    atomicAdd(&g_deg[d], 1);
}

// exclusive scan of g_deg -> g_off (partial), block sums, plus dinv
__global__ void k_scan1_dinv() {
    __shared__ int s[SCAN_BLK];
    int i = blockIdx.x * SCAN_BLK + threadIdx.x;
    int v = (i < N_NODES) ? g_deg[i] : 0;
    if (i < N_NODES) g_dinv[i] = rsqrtf((float)(v + 1));         // +1 self-loop
    s[threadIdx.x] = v;
    __syncthreads();
    for (int o = 1; o < SCAN_BLK; o <<= 1) {
        int t = (threadIdx.x >= o) ? s[threadIdx.x - o] : 0;
        __syncthreads();
        s[threadIdx.x] += t;
        __syncthreads();
    }
    if (i < N_NODES) g_off[i] = s[threadIdx.x] - v;               // exclusive
    if (threadIdx.x == SCAN_BLK - 1) g_bsum[blockIdx.x] = s[threadIdx.x];
}

// ---------------- layer 1 GEMM: h1s = (x @ W1) * dinv[row] ----------------
// (launched as the 4th kernel so ncu -s5 profiles it)
__global__ void k_gemm1(const float* __restrict__ x, const float* __restrict__ W1) {
    __shared__ float sW[IN_CH * HID];   // 8 KB
    for (int t = threadIdx.x; t < IN_CH * HID; t += blockDim.x) sW[t] = W1[t];
    __syncthreads();

    int row = blockIdx.x * blockDim.x + threadIdx.x;
    if (row >= N_NODES) return;

    float acc[HID];
#pragma unroll
    for (int j = 0; j < HID; j++) acc[j] = 0.f;

    const float4* xr = reinterpret_cast<const float4*>(x + (size_t)row * IN_CH);
#pragma unroll 4
    for (int k4 = 0; k4 < IN_CH / 4; k4++) {
        float4 v = xr[k4];
        const float* w = &sW[k4 * 4 * HID];
#pragma unroll
        for (int j = 0; j < HID; j++)
            acc[j] += v.x * w[j] + v.y * w[HID + j] + v.z * w[2 * HID + j] + v.w * w[3 * HID + j];
    }

    float dv = g_dinv[row];
    float4* h = reinterpret_cast<float4*>(g_h1s + (size_t)row * HID);
#pragma unroll
    for (int q = 0; q < HID / 4; q++)
        h[q] = make_float4(acc[4 * q + 0] * dv, acc[4 * q + 1] * dv,
                           acc[4 * q + 2] * dv, acc[4 * q + 3] * dv);
}

__global__ void k_scan2() {     // 1 block, 512 threads; scan 391 block sums
    __shared__ int s[512];
    int v = (threadIdx.x < N_BLK1) ? g_bsum[threadIdx.x] : 0;
    s[threadIdx.x] = v;
    __syncthreads();
    for (int o = 1; o < 512; o <<= 1) {
        int t = (threadIdx.x >= o) ? s[threadIdx.x - o] : 0;
        __syncthreads();
        s[threadIdx.x] += t;
        __syncthreads();
    }
    if (threadIdx.x < N_BLK1) g_bsum[threadIdx.x] = s[threadIdx.x] - v;  // exclusive
}

__global__ void k_scan3() {
    int i = blockIdx.x * blockDim.x + threadIdx.x;
    if (i < N_NODES) {
        int o = g_off[i] + g_bsum[i / SCAN_BLK];
        g_off[i] = o;
        g_cursor[i] = o;
    }
    if (i == 0) g_off[N_NODES] = N_EDGES;
}

__global__ void k_fill(const void* __restrict__ eiv) {
    int e = blockIdx.x * blockDim.x + threadIdx.x;
    if (e >= N_EDGES) return;
    int s, d;
    if (g_is32) {
        const int* p = (const int*)eiv;
        s = p[e]; d = p[N_EDGES + e];
    } else {
        const long long* p = (const long long*)eiv;
        s = (int)p[e]; d = (int)p[N_EDGES + e];
    }
    s = min(max(s, 0), N_NODES - 1);
    d = min(max(d, 0), N_NODES - 1);
    int pos = atomicAdd(&g_cursor[d], 1);
    g_csr[pos] = s;
}

// ---------------- gather layer 1 (fused bias+relu+rescale) ----------------
// warp per node; 8 groups of 4 lanes; 2 independent edge chains per group.
__global__ void k_gather1(const float* __restrict__ b1) {
    int nid = (blockIdx.x * blockDim.x + threadIdx.x) >> 5;
    if (nid >= N_NODES) return;
    int lane = threadIdx.x & 31;
    int grp = lane >> 2, q = lane & 3;

    int beg = g_off[nid], end = g_off[nid + 1];
    const float4* __restrict__ H = reinterpret_cast<const float4*>(g_h1s);

    float4 acc = (grp == 0) ? H[nid * 4 + q] : make_float4(0.f, 0.f, 0.f, 0.f); // self-loop
    int i = beg + grp;
    for (; i + 8 < end; i += 16) {
        int s0 = g_csr[i];
        int s1 = g_csr[i + 8];
        float4 v0 = H[s0 * 4 + q];
        float4 v1 = H[s1 * 4 + q];
        acc.x += v0.x + v1.x; acc.y += v0.y + v1.y;
        acc.z += v0.z + v1.z; acc.w += v0.w + v1.w;
    }
    if (i < end) {
        int s = g_csr[i];
        float4 v = H[s * 4 + q];
        acc.x += v.x; acc.y += v.y; acc.z += v.z; acc.w += v.w;
    }
#pragma unroll
    for (int m = 16; m >= 4; m >>= 1) {
        acc.x += __shfl_xor_sync(0xffffffffu, acc.x, m);
        acc.y += __shfl_xor_sync(0xffffffffu, acc.y, m);
        acc.z += __shfl_xor_sync(0xffffffffu, acc.z, m);
        acc.w += __shfl_xor_sync(0xffffffffu, acc.w, m);
    }
    if (grp == 0) {
        float dv = g_dinv[nid];
        float4 bb = reinterpret_cast<const float4*>(b1)[q];
        float4 r;
        r.x = fmaxf(acc.x * dv + bb.x, 0.f) * dv;
        r.y = fmaxf(acc.y * dv + bb.y, 0.f) * dv;
        r.z = fmaxf(acc.z * dv + bb.z, 0.f) * dv;
        r.w = fmaxf(acc.w * dv + bb.w, 0.f) * dv;
        reinterpret_cast<float4*>(g_gs)[nid * 4 + q] = r;
    }
}

// ---------------- gather layer 2 fused with GEMM2 (+b2) ----------------
__global__ void k_gather2_gemm2(const float* __restrict__ W2,
                                const float* __restrict__ b2,
                                float* __restrict__ out) {
    __shared__ float sW[HID * OUT_CH];                 // 4 KB
    __shared__ __align__(16) float s_a[8][HID];
    for (int t = threadIdx.x; t < HID * OUT_CH; t += blockDim.x) sW[t] = W2[t];
    __syncthreads();

    int w = threadIdx.x >> 5;
    int nid = blockIdx.x * 8 + w;
    if (nid >= N_NODES) return;
    int lane = threadIdx.x & 31;
    int grp = lane >> 2, q = lane & 3;

    int beg = g_off[nid], end = g_off[nid + 1];
    const float4* __restrict__ G = reinterpret_cast<const float4*>(g_gs);

    float4 acc = (grp == 0) ? G[nid * 4 + q] : make_float4(0.f, 0.f, 0.f, 0.f); // self-loop
    int i = beg + grp;
    for (; i + 8 < end; i += 16) {
        int s0 = g_csr[i];
        int s1 = g_csr[i + 8];
        float4 v0 = G[s0 * 4 + q];
        float4 v1 = G[s1 * 4 + q];
        acc.x += v0.x + v1.x; acc.y += v0.y + v1.y;
        acc.z += v0.z + v1.z; acc.w += v0.w + v1.w;
    }
    if (i < end) {
        int s = g_csr[i];
        float4 v = G[s * 4 + q];
        acc.x += v.x; acc.y += v.y; acc.z += v.z; acc.w += v.w;
    }
#pragma unroll
    for (int m = 16; m >= 4; m >>= 1) {
        acc.x += __shfl_xor_sync(0xffffffffu, acc.x, m);
        acc.y += __shfl_xor_sync(0xffffffffu, acc.y, m);
        acc.z += __shfl_xor_sync(0xffffffffu, acc.z, m);
        acc.w += __shfl_xor_sync(0xffffffffu, acc.w, m);
    }
    if (grp == 0) {
        float dv = g_dinv[nid];
        reinterpret_cast<float4*>(&s_a[w][q * 4])[0] =
            make_float4(acc.x * dv, acc.y * dv, acc.z * dv, acc.w * dv);
    }
    __syncwarp();

    // each lane computes cols {lane, lane+32}
    float a0 = b2[lane], a1 = b2[lane + 32];
#pragma unroll
    for (int k = 0; k < HID; k++) {
        float av = s_a[w][k];
        a0 += av * sW[k * OUT_CH + lane];
        a1 += av * sW[k * OUT_CH + lane + 32];
    }
    out[(size_t)nid * OUT_CH + lane]      = a0;
    out[(size_t)nid * OUT_CH + lane + 32] = a1;
}

// ---------------- launch ----------------
extern "C" void kernel_launch(void* const* d_in, const int* in_sizes, int n_in,
                              void* d_out, int out_size) {
    const float* x  = (const float*)d_in[0];
    const void*  ei = (const void*)d_in[1];
    const float* W1 = (const float*)d_in[2];
    const float* b1 = (const float*)d_in[3];
    const float* W2 = (const float*)d_in[4];
    const float* b2 = (const float*)d_in[5];
    float*       out = (float*)d_out;

    const int TB = 256;
    k_init_detect<<<(N_NODES + TB - 1) / TB, TB>>>((const long long*)ei);   // 1
    k_count<<<(N_EDGES + TB - 1) / TB, TB>>>(ei);                           // 2
    k_scan1_dinv<<<N_BLK1, SCAN_BLK>>>();                                   // 3
    k_gemm1<<<(N_NODES + 127) / 128, 128>>>(x, W1);                         // 4 <- profiled
    k_scan2<<<1, 512>>>();                                                  // 5
    k_scan3<<<(N_NODES + TB - 1) / TB, TB>>>();                             // 6
    k_fill<<<(N_EDGES + TB - 1) / TB, TB>>>(ei);                            // 7
    k_gather1<<<N_NODES / 8, TB>>>(b1);                                     // 8 (12500 blocks exact)
    k_gather2_gemm2<<<(N_NODES + 7) / 8, TB>>>(W2, b2, out);                // 9
}